// round 15
// baseline (speedup 1.0000x reference)
#include <cuda_runtime.h>
#include <math.h>
#include <stdint.h>

#define BATCH 512
#define HID   512
#define NCLS  1000
#define MC    4000
#define INV_SIGMA (1.0f/10.0f)

#if defined(__CUDA_ARCH__) && (__CUDA_ARCH__ == 1030) && defined(__CUDA_ARCH_FEAT_SM103_ALL)
#define HAS_TC 1
#else
#define HAS_TC 0
#endif

// ---------------- scratch ----------------
__device__ __align__(16) float g_a[4096];        // ||w_m||^2 (exact fp32)
__device__ __align__(16) float g_fsq[BATCH];     // ||f_b||^2
__device__ __align__(16) float g_Wt[512*4096];   // W^T tf32-RN, stride 4096, m>=4000 zeroed
__device__ __align__(16) float g_G2[80*16384];   // Gram partials: 10 tiles x 8 z
__device__ double g_ap[141], g_a2p[141];         // per-block sum a, sum a^2
__device__ double g_s2p[128], g_usp[128];        // per-block sum s^2, sum u*s
__device__ double g_f2p[160];                    // per-block F2 partials
__device__ unsigned g_ctr = 0;                   // arrival counter (reset each run)

__constant__ int c_ti[10] = {0,0,0,0,1,1,1,2,2,3};
__constant__ int c_tj[10] = {0,1,2,3,1,2,3,2,3,3};

// ---------------- PTX helpers ----------------
__device__ __forceinline__ uint32_t smem_u32(const void* p) {
    uint32_t a;
    asm("{ .reg .u64 t; cvta.to.shared.u64 t, %1; cvt.u32.u64 %0, t; }"
        : "=r"(a) : "l"(p));
    return a;
}
__device__ __forceinline__ uint32_t elect_one() {
    uint32_t pred;
    asm volatile("{\n\t.reg .pred p;\n\telect.sync _|p, 0xFFFFFFFF;\n\t"
                 "selp.b32 %0, 1, 0, p;\n\t}" : "=r"(pred));
    return pred;
}
__device__ __forceinline__ float tf32_rn(float x) {
    float r;
    asm("cvt.rna.tf32.f32 %0, %1;" : "=f"(r) : "f"(x));
    return r;
}
#define MBAR_INIT(addr, cnt) \
    asm volatile("mbarrier.init.shared.b64 [%0], %1;" :: "r"(addr), "r"(cnt) : "memory")
#define MBAR_WAIT(addr, par) do { \
    uint32_t _m = (addr), _p = (par), _d; \
    asm volatile("{\n\t.reg .pred p;\n\t" \
        "mbarrier.try_wait.parity.acquire.cta.shared::cta.b64 p, [%1], %2;\n\t" \
        "selp.b32 %0, 1, 0, p;\n\t}" : "=r"(_d) : "r"(_m), "r"(_p) : "memory"); \
    if (!_d) { \
        asm volatile("{\n\t.reg .pred P1;\n\tWL%=:\n\t" \
            "mbarrier.try_wait.parity.acquire.cta.shared::cta.b64 P1, [%0], %1, 0x989680;\n\t" \
            "@P1 bra.uni WD%=;\n\tbra.uni WL%=;\n\tWD%=:\n\t}" \
            :: "r"(_m), "r"(_p) : "memory"); \
    } } while (0)

#if HAS_TC
#define TC_ALLOC(smem_addr, n) \
    asm volatile("tcgen05.alloc.cta_group::1.sync.aligned.shared::cta.b32 [%0], %1;" \
        :: "r"(smem_addr), "r"(n) : "memory")
#define TC_DEALLOC(tmem, n) \
    asm volatile("tcgen05.dealloc.cta_group::1.sync.aligned.b32 %0, %1;" :: "r"(tmem), "r"(n))
#define TC_RELINQ() \
    asm volatile("tcgen05.relinquish_alloc_permit.cta_group::1.sync.aligned;")
#define TC_COMMIT(mbar) \
    asm volatile("tcgen05.commit.cta_group::1.mbarrier::arrive::one.shared::cluster.b64 [%0];" \
        :: "r"(mbar) : "memory")
#define TC_FENCE_AFTER() asm volatile("tcgen05.fence::after_thread_sync;" ::: "memory")
#define TC_FENCE_BEFORE() asm volatile("tcgen05.fence::before_thread_sync;" ::: "memory")
#define TC_WAIT_LD() asm volatile("tcgen05.wait::ld.sync.aligned;" ::: "memory")
#define LDTM_X32(r, addr) \
    asm volatile("tcgen05.ld.sync.aligned.32x32b.x32.b32 " \
        "{%0,%1,%2,%3,%4,%5,%6,%7,%8,%9,%10,%11,%12,%13,%14,%15," \
        "%16,%17,%18,%19,%20,%21,%22,%23,%24,%25,%26,%27,%28,%29,%30,%31}, [%32];" \
        : "=r"((r)[0]),"=r"((r)[1]),"=r"((r)[2]),"=r"((r)[3]), \
          "=r"((r)[4]),"=r"((r)[5]),"=r"((r)[6]),"=r"((r)[7]), \
          "=r"((r)[8]),"=r"((r)[9]),"=r"((r)[10]),"=r"((r)[11]), \
          "=r"((r)[12]),"=r"((r)[13]),"=r"((r)[14]),"=r"((r)[15]), \
          "=r"((r)[16]),"=r"((r)[17]),"=r"((r)[18]),"=r"((r)[19]), \
          "=r"((r)[20]),"=r"((r)[21]),"=r"((r)[22]),"=r"((r)[23]), \
          "=r"((r)[24]),"=r"((r)[25]),"=r"((r)[26]),"=r"((r)[27]), \
          "=r"((r)[28]),"=r"((r)[29]),"=r"((r)[30]),"=r"((r)[31]) \
        : "r"(addr))

static __device__ __forceinline__ uint64_t make_desc(uint32_t addr) {
    const uint64_t base = (uint64_t(2) << 61) | (uint64_t(1) << 46)
                        | (uint64_t(64) << 32) | (uint64_t(1) << 16);
    return base | ((uint64_t)(addr >> 4) & 0x3FFF);
}
__device__ __forceinline__ void mma_tf32(uint32_t d, uint64_t ad, uint64_t bd,
                                         uint32_t idesc, uint32_t en) {
    asm volatile("{\n\t.reg .pred p;\n\tsetp.ne.u32 p, %5, 0;\n\t"
        "tcgen05.mma.cta_group::1.kind::tf32 [%0], %1, %2, %3, {%4,%4,%4,%4}, p;\n\t}"
        :: "r"(d), "l"(ad), "l"(bd), "r"(idesc), "r"(0u), "r"(en) : "memory");
}
#endif  // HAS_TC

__device__ __forceinline__ uint32_t swz(uint32_t o) { return o ^ ((o >> 3) & 0x70); }

__device__ __forceinline__ void cp16(uint32_t dst, const void* src, bool valid) {
    int sz = valid ? 16 : 0;
    asm volatile("cp.async.cg.shared.global [%0], [%1], 16, %2;"
                 :: "r"(dst), "l"(src), "r"(sz));
}

// ---------------- transpose + tf32-RN round; zero-pads m in [4000,4096) -------
// grid (16, 128): k-tile x m-tile
__global__ void __launch_bounds__(256) k_transpose(const float* __restrict__ W) {
    __shared__ float tile[32][33];
    int k0 = (blockIdx.x & 15) * 32, m0 = (int)blockIdx.y * 32;
    int x = threadIdx.x & 31, y = threadIdx.x >> 5;
    #pragma unroll
    for (int i = 0; i < 4; i++) {
        int m = m0 + y + i * 8;
        tile[y + i * 8][x] = (m < MC) ? W[(size_t)m * HID + k0 + x] : 0.f;
    }
    __syncthreads();
    #pragma unroll
    for (int i = 0; i < 4; i++)
        g_Wt[(size_t)(k0 + y + i * 8) * 4096 + m0 + x] = tf32_rn(tile[x][y + i * 8]);
}

// ---------------- pre: a_m, fsq + per-block fp64 (sum a, sum a^2) ----------------
__global__ void __launch_bounds__(256) k_pre(const float* __restrict__ W,
                                             const float* __restrict__ F) {
    __shared__ double sda[8], sda2[8];
    int tid = threadIdx.x, wid = tid >> 5, lane = tid & 31;
    int warp = (int)blockIdx.x * 8 + wid;
    int r0 = warp * 4;
    bool isW = (r0 < MC);
    const float* base = isW ? W : F;
    int rb = isW ? r0 : (r0 - MC);
    float4 v[4][4];
    #pragma unroll
    for (int j = 0; j < 4; j++)
        #pragma unroll
        for (int q = 0; q < 4; q++)
            v[j][q] = reinterpret_cast<const float4*>(
                base + (size_t)(rb + j) * HID)[lane + q * 32];
    float acc[4];
    #pragma unroll
    for (int j = 0; j < 4; j++) {
        float a = 0.f;
        #pragma unroll
        for (int q = 0; q < 4; q++)
            a += v[j][q].x*v[j][q].x + v[j][q].y*v[j][q].y
               + v[j][q].z*v[j][q].z + v[j][q].w*v[j][q].w;
        acc[j] = a;
    }
    #pragma unroll
    for (int o = 16; o > 0; o >>= 1)
        #pragma unroll
        for (int j = 0; j < 4; j++)
            acc[j] += __shfl_down_sync(0xffffffffu, acc[j], o);
    if (lane == 0) {
        double da = 0.0, da2 = 0.0;
        #pragma unroll
        for (int j = 0; j < 4; j++) {
            if (isW) {
                g_a[r0 + j] = acc[j];
                double a = (double)acc[j];
                da += a; da2 += a * a;
            } else {
                g_fsq[rb + j] = acc[j];
            }
        }
        sda[wid] = da; sda2[wid] = da2;
    }
    __syncthreads();
    if (tid == 0) {
        double da = 0.0, da2 = 0.0;
        #pragma unroll
        for (int j = 0; j < 8; j++) { da += sda[j]; da2 += sda2[j]; }
        g_ap[blockIdx.x] = da; g_a2p[blockIdx.x] = da2;
    }
}

// ---------------- su: 128 blocks x 8 warps; 2 warps per k (half-rows) ----------
__global__ void __launch_bounds__(256) k_su() {
    __shared__ float sh_s[4][2], sh_u[4][2];
    __shared__ double sh_d[4][2];
    int tid = threadIdx.x, wid = tid >> 5, lane = tid & 31;
    int kl = wid >> 1, half = wid & 1;
    int k = (int)blockIdx.x * 4 + kl;
    const float4* row = reinterpret_cast<const float4*>(g_Wt + (size_t)k * 4096)
                      + half * 500;
    const float4* av  = reinterpret_cast<const float4*>(g_a) + half * 500;
    float s = 0.f, u = 0.f;
    #pragma unroll
    for (int q = 0; q < 16; q++) {
        int idx = lane + q * 32;
        if (idx < 500) {
            float4 w = row[idx];
            float4 a = av[idx];
            s += w.x + w.y + w.z + w.w;
            u += a.x*w.x + a.y*w.y + a.z*w.z + a.w*w.w;
        }
    }
    #pragma unroll
    for (int o = 16; o > 0; o >>= 1) {
        s += __shfl_down_sync(0xffffffffu, s, o);
        u += __shfl_down_sync(0xffffffffu, u, o);
    }
    if (lane == 0) { sh_s[kl][half] = s; sh_u[kl][half] = u; }
    __syncthreads();
    if (tid < 4) {
        float sk = sh_s[tid][0] + sh_s[tid][1];
        float uk = sh_u[tid][0] + sh_u[tid][1];
        sh_d[tid][0] = (double)sk * (double)sk;
        sh_d[tid][1] = (double)uk * (double)sk;
    }
    __syncthreads();
    if (tid == 0) {
        double s2 = 0.0, us = 0.0;
        #pragma unroll
        for (int j = 0; j < 4; j++) { s2 += sh_d[j][0]; us += sh_d[j][1]; }
        g_s2p[blockIdx.x] = s2; g_usp[blockIdx.x] = us;
    }
}

// ---------------- pipeline: KC=64 (two 16KB sub-tiles), 3 stages ----------------
#define STG       3
#define SUB_BYTES 16384
#define STG_BYTES 32768                     // 2 sub-tiles (k/m halves)
#define OFF_A     1024
#define OFF_B     (1024 + STG*STG_BYTES)
#define SMEM_TC   (1024 + 2*STG*STG_BYTES)  // 197,632 B (1 CTA/SM; grid<148 anyway)
#define IDESC_TF32 ((1u<<4) | (2u<<7) | (2u<<10) | (16u<<17) | (8u<<24))
#define NCHUNK  8                            // 512 / 64

#if HAS_TC
// 2048 (h,row,seg) triples per operand, 8 per thread
__device__ __forceinline__ void gram_load_chunk(uint32_t sb, int stage, int c,
                                                int K0, int L0, int mbase, int tid) {
    int moff = mbase + c * 64;
    uint32_t dA = sb + OFF_A + stage * STG_BYTES;
    uint32_t dB = sb + OFF_B + stage * STG_BYTES;
    #pragma unroll
    for (int p = 0; p < 8; p++) {
        int idx = p * 256 + tid;
        int h = idx >> 10, rem = idx & 1023;
        int r = rem >> 3, seg = rem & 7;
        uint32_t off = (uint32_t)(h * SUB_BYTES) + swz((uint32_t)(r * 128 + seg * 16));
        int col = moff + h * 32 + seg * 4;
        cp16(dA + off, g_Wt + (size_t)(K0 + r) * 4096 + col, true);
        cp16(dB + off, g_Wt + (size_t)(L0 + r) * 4096 + col, true);
    }
}
__device__ __forceinline__ void fw_load_chunk(uint32_t sb, int stage, int c,
                                              const float* __restrict__ W,
                                              const float* __restrict__ F,
                                              int m0, int b0, int tid) {
    int kc = c * 64;
    uint32_t dA = sb + OFF_A + stage * STG_BYTES;
    uint32_t dB = sb + OFF_B + stage * STG_BYTES;
    #pragma unroll
    for (int p = 0; p < 8; p++) {
        int idx = p * 256 + tid;
        int h = idx >> 10, rem = idx & 1023;
        int r = rem >> 3, seg = rem & 7;
        uint32_t off = (uint32_t)(h * SUB_BYTES) + swz((uint32_t)(r * 128 + seg * 16));
        int col = kc + h * 32 + seg * 4;
        int m = m0 + r;
        bool v = (m < MC);
        cp16(dA + off, W + (size_t)(v ? m : 0) * HID + col, v);
        cp16(dB + off, F + (size_t)(b0 + r) * HID + col, true);
    }
}
// 8 MMAs covering one K=64 chunk (2 sub-tiles x 4 K8-steps)
__device__ __forceinline__ void issue_chunk_mmas(uint32_t tmem, uint32_t sA,
                                                 uint32_t sB, bool first) {
    #pragma unroll
    for (int h = 0; h < 2; h++) {
        uint64_t ad = make_desc(sA + h * SUB_BYTES);
        uint64_t bd = make_desc(sB + h * SUB_BYTES);
        #pragma unroll
        for (int k = 0; k < 4; k++)
            mma_tf32(tmem, ad + k * 2, bd + k * 2, IDESC_TF32,
                     (!first || h > 0 || k > 0) ? 1u : 0u);
    }
}
#endif

// gram: grid 80 = 10 tiles x 8 z (512 m each, tail zero-padded)
__global__ void __launch_bounds__(256, 1) k_gram_tc() {
    int tid = threadIdx.x, wid = tid >> 5, lane = tid & 31;
    int t = blockIdx.x >> 3, z = blockIdx.x & 7;
    int K0 = c_ti[t] * 128, L0 = c_tj[t] * 128;
    int mbase = z * 512;
#if HAS_TC
    extern __shared__ char smem[];
    uint32_t sb = smem_u32(smem);

    if (tid < 3) MBAR_INIT(sb + tid * 8, 1);
    if (wid == 0) { TC_ALLOC(sb + 32, 128); TC_RELINQ(); }
    __syncthreads();
    uint32_t tmem;
    asm volatile("ld.shared.b32 %0, [%1];" : "=r"(tmem) : "r"(sb + 32));

    #pragma unroll
    for (int c0 = 0; c0 < 2; c0++) {
        gram_load_chunk(sb, c0, c0, K0, L0, mbase, tid);
        asm volatile("cp.async.commit_group;" ::: "memory");
    }
    uint32_t phv = 0;
    for (int c = 0; c < NCHUNK; c++) {
        int s = c % 3;
        if (c + 2 < NCHUNK) {
            int so = (c + 2) % 3;
            if (c >= 1) {
                MBAR_WAIT(sb + so * 8, (phv >> so) & 1u);
                phv ^= (1u << so);
            }
            gram_load_chunk(sb, so, c + 2, K0, L0, mbase, tid);
        }
        asm volatile("cp.async.commit_group;" ::: "memory");
        asm volatile("cp.async.wait_group 2;" ::: "memory");
        __syncthreads();
        if (wid == 0 && elect_one()) {
            asm volatile("fence.proxy.async.shared::cta;" ::: "memory");
            issue_chunk_mmas(tmem, sb + OFF_A + s * STG_BYTES,
                             sb + OFF_B + s * STG_BYTES, c == 0);
            TC_COMMIT(sb + s * 8);
        }
    }
    __syncthreads();
    {
        int so = (NCHUNK - 1) % 3;
        MBAR_WAIT(sb + so * 8, (phv >> so) & 1u);
    }
    TC_FENCE_AFTER();

    float* dst = g_G2 + ((size_t)blockIdx.x << 14);
    int row = (wid & 3) * 32 + lane;
    int cb = (wid >> 2) * 64;
    #pragma unroll
    for (int j0 = 0; j0 < 64; j0 += 32) {
        uint32_t r[32];
        LDTM_X32(r, tmem + cb + j0);
        TC_WAIT_LD();
        #pragma unroll
        for (int j4 = 0; j4 < 8; j4++) {
            float4 v = make_float4(__uint_as_float(r[j4*4+0]), __uint_as_float(r[j4*4+1]),
                                   __uint_as_float(r[j4*4+2]), __uint_as_float(r[j4*4+3]));
            *reinterpret_cast<float4*>(&dst[(size_t)row * 128 + cb + j0 + j4 * 4]) = v;
        }
    }
    TC_FENCE_BEFORE();
    __syncthreads();
    if (wid == 0) TC_DEALLOC(tmem, 128);
#else
    float* dst = g_G2 + ((size_t)blockIdx.x << 14);
    for (int e = tid; e < 16384; e += blockDim.x) {
        int k = K0 + (e >> 7), l = L0 + (e & 127);
        float acc = 0.f;
        for (int m = 0; m < 512; m++)
            acc = fmaf(g_Wt[(size_t)k * 4096 + mbase + m],
                       g_Wt[(size_t)l * 4096 + mbase + m], acc);
        dst[e] = acc;
    }
#endif
}

__global__ void __launch_bounds__(256, 1) k_fw_tc(const float* __restrict__ F,
                                                  const float* __restrict__ W,
                                                  float* __restrict__ out) {
#if HAS_TC
    extern __shared__ char smem[];
    uint32_t sb = smem_u32(smem);
    int tid = threadIdx.x, wid = tid >> 5, lane = tid & 31;
    int m0 = (int)blockIdx.x * 128, b0 = (int)blockIdx.y * 128;

    if (tid < 3) MBAR_INIT(sb + tid * 8, 1);
    if (wid == 0) { TC_ALLOC(sb + 32, 128); TC_RELINQ(); }
    __syncthreads();
    uint32_t tmem;
    asm volatile("ld.shared.b32 %0, [%1];" : "=r"(tmem) : "r"(sb + 32));

    #pragma unroll
    for (int c0 = 0; c0 < 2; c0++) {
        fw_load_chunk(sb, c0, c0, W, F, m0, b0, tid);
        asm volatile("cp.async.commit_group;" ::: "memory");
    }
    uint32_t phv = 0;
    for (int c = 0; c < NCHUNK; c++) {
        int s = c % 3;
        if (c + 2 < NCHUNK) {
            int so = (c + 2) % 3;
            if (c >= 1) {
                MBAR_WAIT(sb + so * 8, (phv >> so) & 1u);
                phv ^= (1u << so);
            }
            fw_load_chunk(sb, so, c + 2, W, F, m0, b0, tid);
        }
        asm volatile("cp.async.commit_group;" ::: "memory");
        asm volatile("cp.async.wait_group 2;" ::: "memory");
        __syncthreads();
        if (wid == 0 && elect_one()) {
            asm volatile("fence.proxy.async.shared::cta;" ::: "memory");
            issue_chunk_mmas(tmem, sb + OFF_A + s * STG_BYTES,
                             sb + OFF_B + s * STG_BYTES, c == 0);
            TC_COMMIT(sb + s * 8);
        }
    }
    __syncthreads();
    {
        int so = (NCHUNK - 1) % 3;
        MBAR_WAIT(sb + so * 8, (phv >> so) & 1u);
    }
    TC_FENCE_AFTER();

    // epilogue: warps 0-3 -> cols 0-63, warps 4-7 -> cols 64-127
    int m = m0 + (wid & 3) * 32 + lane;
    int cb = (wid >> 2) * 64;
    float a = (m < MC) ? __ldg(&g_a[m]) : __int_as_float(0x7f800000);
    int grp = m >> 2;
    #pragma unroll
    for (int j0 = 0; j0 < 64; j0 += 32) {
        uint32_t r[32];
        LDTM_X32(r, tmem + cb + j0);
        TC_WAIT_LD();
        #pragma unroll
        for (int jj = 0; jj < 32; jj++) {
            float fw = __uint_as_float(r[jj]);
            float x = fmaf(-2.f, fw, a);
            x = fminf(x, __shfl_xor_sync(0xffffffffu, x, 1));
            x = fminf(x, __shfl_xor_sync(0xffffffffu, x, 2));
            if ((lane & 3) == 0 && m < MC) {
                int b = b0 + cb + j0 + jj;
                out[(size_t)b * (NCLS + 1) + grp] =
                    expf(-(__ldg(&g_fsq[b]) + x) * INV_SIGMA);
            }
        }
    }
    TC_FENCE_BEFORE();
    __syncthreads();
    if (wid == 0) TC_DEALLOC(tmem, 128);
#else
    int tid = threadIdx.x;
    int m0 = (int)blockIdx.x * 128, b0 = (int)blockIdx.y * 128;
    int m = m0 + (tid & 127);
    if (m >= MC || tid >= 128) return;
    float a = g_a[m];
    int grp = m >> 2;
    const float* wrow = W + (size_t)m * HID;
    for (int jb = 0; jb < 128; jb++) {
        int b = b0 + jb;
        const float* frow = F + (size_t)b * HID;
        float dot = 0.f;
        for (int k = 0; k < HID; k++) dot = fmaf(wrow[k], frow[k], dot);
        float x = fmaf(-2.f, dot, a);
        x = fminf(x, __shfl_xor_sync(0xffffffffu, x, 1));
        x = fminf(x, __shfl_xor_sync(0xffffffffu, x, 2));
        if ((tid & 3) == 0)
            out[(size_t)b * (NCLS + 1) + grp] =
                expf(-(g_fsq[b] + x) * INV_SIGMA);
    }
#endif
}

// ---------------- f2 + fused finalize (last-arriving block) ----------------
__global__ void __launch_bounds__(256) k_f2fin(float* __restrict__ out) {
    __shared__ double sd[8], sd2[8], sd3[8], sd4[8], sd5[8];
    __shared__ bool is_last;
    __shared__ float rw_s;
    int tid = threadIdx.x, wid = tid >> 5, lane = tid & 31;

    double acc = 0.0;
    for (int i = (int)blockIdx.x * 256 + tid; i < 10 * 16384; i += 160 * 256) {
        int t = i >> 14, e = i & 16383;
        float g = 0.f;
        #pragma unroll
        for (int z = 0; z < 8; z++) g += g_G2[((size_t)(t * 8 + z) << 14) + e];
        double w = (c_ti[t] == c_tj[t]) ? 1.0 : 2.0;
        acc += w * (double)g * (double)g;
    }
    #pragma unroll
    for (int o = 16; o > 0; o >>= 1)
        acc += __shfl_down_sync(0xffffffffu, acc, o);
    if (lane == 0) sd[wid] = acc;
    __syncthreads();
    if (tid == 0) {
        double f = 0.0;
        #pragma unroll
        for (int j = 0; j < 8; j++) f += sd[j];
        g_f2p[blockIdx.x] = f;
    }
    __threadfence();
    __syncthreads();
    if (tid == 0) {
        unsigned v = atomicAdd(&g_ctr, 1u);
        is_last = (v == 159u);
    }
    __syncthreads();
    if (!is_last) return;
    if (tid == 0) g_ctr = 0;
    __threadfence();

    double la  = (tid < 141) ? g_ap[tid]  : 0.0;
    double la2 = (tid < 141) ? g_a2p[tid] : 0.0;
    double ls2 = (tid < 128) ? g_s2p[tid] : 0.0;
    double lus = (tid < 128) ? g_usp[tid] : 0.0;
    double lf2 = (tid < 160) ? g_f2p[tid] : 0.0;
    #pragma unroll
    for (int o = 16; o > 0; o >>= 1) {
        la  += __shfl_down_sync(0xffffffffu, la,  o);
        la2 += __shfl_down_sync(0xffffffffu, la2, o);
        ls2 += __shfl_down_sync(0xffffffffu, ls2, o);
        lus += __shfl_down_sync(0xffffffffu, lus, o);
        lf2 += __shfl_down_sync(0xffffffffu, lf2, o);
    }
    if (lane == 0) { sd[wid]=la; sd2[wid]=la2; sd3[wid]=ls2; sd4[wid]=lus; sd5[wid]=lf2; }
    __syncthreads();
    if (tid == 0) {
        double sum_a=0, sum_a2=0, s2=0, sum_at=0, F2=0;
        #pragma unroll
        for (int j = 0; j < 8; j++) {
            sum_a += sd[j]; sum_a2 += sd2[j]; s2 += sd3[j];
            sum_at += sd4[j]; F2 += sd5[j];
        }
        double mc = (double)MC;
        double denom = 2.0 / (mc * mc - mc);
        double S1 = mc * sum_a - s2;
        double mu = denom * S1;
        double S2 = mc * sum_a2 + sum_a * sum_a + 2.0 * F2 - 4.0 * sum_at;
        rw_s = (float)(denom * S2 - mu * mu);
    }
    __syncthreads();
    #pragma unroll
    for (int j = 0; j < 2; j++)
        out[(size_t)(tid * 2 + j) * (NCLS + 1) + NCLS] = rw_s;
}

extern "C" void kernel_launch(void* const* d_in, const int* in_sizes, int n_in,
                              void* d_out, int out_size) {
    const float* F = (const float*)d_in[0];   // [512,512]
    const float* W = (const float*)d_in[1];   // [4000,512]
    float* out = (float*)d_out;               // [512,1001]
    (void)in_sizes; (void)n_in; (void)out_size;

    static bool inited = false;
    static cudaStream_t s1, s2;
    static cudaEvent_t evA, evT, evP, evS, evB;
    if (!inited) {
        cudaFuncSetAttribute(k_fw_tc, cudaFuncAttributeMaxDynamicSharedMemorySize,
                             SMEM_TC);
        cudaFuncSetAttribute(k_gram_tc, cudaFuncAttributeMaxDynamicSharedMemorySize,
                             SMEM_TC);
        cudaStreamCreateWithFlags(&s1, cudaStreamNonBlocking);
        cudaStreamCreateWithFlags(&s2, cudaStreamNonBlocking);
        cudaEventCreateWithFlags(&evA, cudaEventDisableTiming);
        cudaEventCreateWithFlags(&evT, cudaEventDisableTiming);
        cudaEventCreateWithFlags(&evP, cudaEventDisableTiming);
        cudaEventCreateWithFlags(&evS, cudaEventDisableTiming);
        cudaEventCreateWithFlags(&evB, cudaEventDisableTiming);
        inited = true;
    }

    // fork
    cudaEventRecord(evA, 0);
    cudaStreamWaitEvent(s1, evA, 0);

    // chain 0 (default): transpose(+pad) -> gram
    k_transpose<<<dim3(16, 128), 256>>>(W);
    cudaEventRecord(evT, 0);                  // Wt ready
    k_gram_tc<<<80, 256, SMEM_TC>>>();

    // chain 1 (s1): pre -> fw
    k_pre<<<141, 256, 0, s1>>>(W, F);
    cudaEventRecord(evP, s1);
    k_fw_tc<<<dim3(32, 4), 256, SMEM_TC, s1>>>(F, W, out);
    cudaEventRecord(evB, s1);

    // chain 2 (s2): su (needs Wt + a) — off the critical path
    cudaStreamWaitEvent(s2, evT, 0);
    cudaStreamWaitEvent(s2, evP, 0);
    k_su<<<128, 256, 0, s2>>>();
    cudaEventRecord(evS, s2);

    // join: f2 + fused finalize
    cudaStreamWaitEvent(0, evB, 0);
    cudaStreamWaitEvent(0, evS, 0);
    k_f2fin<<<160, 256>>>(out);
}

// round 16
// speedup vs baseline: 1.0471x; 1.0471x over previous
#include <cuda_runtime.h>
#include <math.h>
#include <stdint.h>

#define BATCH 512
#define HID   512
#define NCLS  1000
#define MC    4000
#define INV_SIGMA (1.0f/10.0f)

#if defined(__CUDA_ARCH__) && (__CUDA_ARCH__ == 1030) && defined(__CUDA_ARCH_FEAT_SM103_ALL)
#define HAS_TC 1
#else
#define HAS_TC 0
#endif

// ---------------- scratch ----------------
__device__ __align__(16) float g_a[4096];        // ||w_m||^2
__device__ __align__(16) float g_fsq[BATCH];     // ||f_b||^2
__device__ __align__(16) float g_Wt[512*4096];   // W^T tf32-RN, stride 4096, m>=4000 zeroed
__device__ __align__(16) float g_G2[40*16384];   // Gram partials: 10 tiles x 4 z
__device__ double g_ap[141], g_a2p[141];         // per-block sum a, sum a^2
__device__ double g_s2p[32], g_usp[32];          // per-block sum s^2, sum u*s
__device__ double g_f2p[160];                    // per-block F2 partials
__device__ unsigned g_ctr = 0;

__constant__ int c_ti[10] = {0,0,0,0,1,1,1,2,2,3};
__constant__ int c_tj[10] = {0,1,2,3,1,2,3,2,3,3};

// ---------------- PTX helpers ----------------
__device__ __forceinline__ uint32_t smem_u32(const void* p) {
    uint32_t a;
    asm("{ .reg .u64 t; cvta.to.shared.u64 t, %1; cvt.u32.u64 %0, t; }"
        : "=r"(a) : "l"(p));
    return a;
}
__device__ __forceinline__ uint32_t elect_one() {
    uint32_t pred;
    asm volatile("{\n\t.reg .pred p;\n\telect.sync _|p, 0xFFFFFFFF;\n\t"
                 "selp.b32 %0, 1, 0, p;\n\t}" : "=r"(pred));
    return pred;
}
__device__ __forceinline__ float tf32_rn(float x) {
    float r;
    asm("cvt.rna.tf32.f32 %0, %1;" : "=f"(r) : "f"(x));
    return r;
}
#define MBAR_INIT(addr, cnt) \
    asm volatile("mbarrier.init.shared.b64 [%0], %1;" :: "r"(addr), "r"(cnt) : "memory")
#define MBAR_WAIT(addr, par) do { \
    uint32_t _m = (addr), _p = (par), _d; \
    asm volatile("{\n\t.reg .pred p;\n\t" \
        "mbarrier.try_wait.parity.acquire.cta.shared::cta.b64 p, [%1], %2;\n\t" \
        "selp.b32 %0, 1, 0, p;\n\t}" : "=r"(_d) : "r"(_m), "r"(_p) : "memory"); \
    if (!_d) { \
        asm volatile("{\n\t.reg .pred P1;\n\tWL%=:\n\t" \
            "mbarrier.try_wait.parity.acquire.cta.shared::cta.b64 P1, [%0], %1, 0x989680;\n\t" \
            "@P1 bra.uni WD%=;\n\tbra.uni WL%=;\n\tWD%=:\n\t}" \
            :: "r"(_m), "r"(_p) : "memory"); \
    } } while (0)

#if HAS_TC
#define TC_ALLOC(smem_addr, n) \
    asm volatile("tcgen05.alloc.cta_group::1.sync.aligned.shared::cta.b32 [%0], %1;" \
        :: "r"(smem_addr), "r"(n) : "memory")
#define TC_DEALLOC(tmem, n) \
    asm volatile("tcgen05.dealloc.cta_group::1.sync.aligned.b32 %0, %1;" :: "r"(tmem), "r"(n))
#define TC_RELINQ() \
    asm volatile("tcgen05.relinquish_alloc_permit.cta_group::1.sync.aligned;")
#define TC_COMMIT(mbar) \
    asm volatile("tcgen05.commit.cta_group::1.mbarrier::arrive::one.shared::cluster.b64 [%0];" \
        :: "r"(mbar) : "memory")
#define TC_FENCE_AFTER() asm volatile("tcgen05.fence::after_thread_sync;" ::: "memory")
#define TC_FENCE_BEFORE() asm volatile("tcgen05.fence::before_thread_sync;" ::: "memory")
#define TC_WAIT_LD() asm volatile("tcgen05.wait::ld.sync.aligned;" ::: "memory")
#define LDTM_X32(r, addr) \
    asm volatile("tcgen05.ld.sync.aligned.32x32b.x32.b32 " \
        "{%0,%1,%2,%3,%4,%5,%6,%7,%8,%9,%10,%11,%12,%13,%14,%15," \
        "%16,%17,%18,%19,%20,%21,%22,%23,%24,%25,%26,%27,%28,%29,%30,%31}, [%32];" \
        : "=r"((r)[0]),"=r"((r)[1]),"=r"((r)[2]),"=r"((r)[3]), \
          "=r"((r)[4]),"=r"((r)[5]),"=r"((r)[6]),"=r"((r)[7]), \
          "=r"((r)[8]),"=r"((r)[9]),"=r"((r)[10]),"=r"((r)[11]), \
          "=r"((r)[12]),"=r"((r)[13]),"=r"((r)[14]),"=r"((r)[15]), \
          "=r"((r)[16]),"=r"((r)[17]),"=r"((r)[18]),"=r"((r)[19]), \
          "=r"((r)[20]),"=r"((r)[21]),"=r"((r)[22]),"=r"((r)[23]), \
          "=r"((r)[24]),"=r"((r)[25]),"=r"((r)[26]),"=r"((r)[27]), \
          "=r"((r)[28]),"=r"((r)[29]),"=r"((r)[30]),"=r"((r)[31]) \
        : "r"(addr))

static __device__ __forceinline__ uint64_t make_desc(uint32_t addr) {
    const uint64_t base = (uint64_t(2) << 61) | (uint64_t(1) << 46)
                        | (uint64_t(64) << 32) | (uint64_t(1) << 16);
    return base | ((uint64_t)(addr >> 4) & 0x3FFF);
}
__device__ __forceinline__ void mma_tf32(uint32_t d, uint64_t ad, uint64_t bd,
                                         uint32_t idesc, uint32_t en) {
    asm volatile("{\n\t.reg .pred p;\n\tsetp.ne.u32 p, %5, 0;\n\t"
        "tcgen05.mma.cta_group::1.kind::tf32 [%0], %1, %2, %3, {%4,%4,%4,%4}, p;\n\t}"
        :: "r"(d), "l"(ad), "l"(bd), "r"(idesc), "r"(0u), "r"(en) : "memory");
}
#endif  // HAS_TC

__device__ __forceinline__ uint32_t swz(uint32_t o) { return o ^ ((o >> 3) & 0x70); }

__device__ __forceinline__ void cp16(uint32_t dst, const void* src, bool valid) {
    int sz = valid ? 16 : 0;
    asm volatile("cp.async.cg.shared.global [%0], [%1], 16, %2;"
                 :: "r"(dst), "l"(src), "r"(sz));
}

#define IDESC_TF32 ((1u<<4) | (2u<<7) | (2u<<10) | (16u<<17) | (8u<<24))
#define SUB_BYTES 16384
// gram: stage = A(32K)+B(32K) = 64K; 2 stages
#define G_STG 65536
// fw: stage = A0+A1+B = 96K; 2 stages
#define F_STG 98304
#define SMEM_TC (1024 + 2*F_STG)   // 197,632 B

// ================= STAGE 1: transpose (0..2047) || pre (2048..2188) =============
__global__ void __launch_bounds__(256) k_stage1(const float* __restrict__ W,
                                                const float* __restrict__ F) {
    __shared__ float tile[32][33];
    int tid = threadIdx.x;
    if (blockIdx.x < 2048) {
        int k0 = ((int)blockIdx.x & 15) * 32, m0 = ((int)blockIdx.x >> 4) * 32;
        int x = tid & 31, y = tid >> 5;
        #pragma unroll
        for (int i = 0; i < 4; i++) {
            int m = m0 + y + i * 8;
            tile[y + i * 8][x] = (m < MC) ? W[(size_t)m * HID + k0 + x] : 0.f;
        }
        __syncthreads();
        #pragma unroll
        for (int i = 0; i < 4; i++)
            g_Wt[(size_t)(k0 + y + i * 8) * 4096 + m0 + x] = tf32_rn(tile[x][y + i * 8]);
    } else {
        __shared__ double sda[8], sda2[8];
        int blk = (int)blockIdx.x - 2048;          // 0..140
        int wid = tid >> 5, lane = tid & 31;
        int warp = blk * 8 + wid;
        int r0 = warp * 4;
        bool isW = (r0 < MC);
        const float* base = isW ? W : F;
        int rb = isW ? r0 : (r0 - MC);
        float4 v[4][4];
        #pragma unroll
        for (int j = 0; j < 4; j++)
            #pragma unroll
            for (int q = 0; q < 4; q++)
                v[j][q] = reinterpret_cast<const float4*>(
                    base + (size_t)(rb + j) * HID)[lane + q * 32];
        float acc[4];
        #pragma unroll
        for (int j = 0; j < 4; j++) {
            float a = 0.f;
            #pragma unroll
            for (int q = 0; q < 4; q++)
                a += v[j][q].x*v[j][q].x + v[j][q].y*v[j][q].y
                   + v[j][q].z*v[j][q].z + v[j][q].w*v[j][q].w;
            acc[j] = a;
        }
        #pragma unroll
        for (int o = 16; o > 0; o >>= 1)
            #pragma unroll
            for (int j = 0; j < 4; j++)
                acc[j] += __shfl_down_sync(0xffffffffu, acc[j], o);
        if (lane == 0) {
            double da = 0.0, da2 = 0.0;
            #pragma unroll
            for (int j = 0; j < 4; j++) {
                if (isW) {
                    g_a[r0 + j] = acc[j];
                    double a = (double)acc[j];
                    da += a; da2 += a * a;
                } else {
                    g_fsq[rb + j] = acc[j];
                }
            }
            sda[wid] = da; sda2[wid] = da2;
        }
        __syncthreads();
        if (tid == 0) {
            double da = 0.0, da2 = 0.0;
            #pragma unroll
            for (int j = 0; j < 8; j++) { da += sda[j]; da2 += sda2[j]; }
            g_ap[blk] = da; g_a2p[blk] = da2;
        }
    }
}

// ================= STAGE 2: gram(0..39) || fw(40..103) || su(104..135) ==========
#if HAS_TC
// gram chunk: A/B 2 sub-tiles each, 4096 cp16, 16/thread
__device__ __forceinline__ void gram_load_chunk(uint32_t sb, int stage, int c,
                                                int K0, int L0, int mbase, int tid) {
    uint32_t st = sb + 1024 + stage * G_STG;
    #pragma unroll
    for (int p = 0; p < 16; p++) {
        int idx = p * 256 + tid;
        int op = idx >> 11, rem = idx & 2047;
        int h = rem >> 10, r = (rem >> 3) & 127, seg = rem & 7;
        uint32_t off = (uint32_t)(op * 2 * SUB_BYTES + h * SUB_BYTES)
                     + swz((uint32_t)(r * 128 + seg * 16));
        int row = (op == 0 ? K0 : L0) + r;
        int col = mbase + c * 64 + h * 32 + seg * 4;
        cp16(st + off, g_Wt + (size_t)row * 4096 + col, true);
    }
}
// fw chunk: A0/A1/B 2 sub-tiles each, 6144 cp16, 24/thread
__device__ __forceinline__ void fw_load_chunk(uint32_t sb, int stage, int c,
                                              const float* __restrict__ W,
                                              const float* __restrict__ F,
                                              int m0, int b0, int tid) {
    uint32_t st = sb + 1024 + stage * F_STG;
    #pragma unroll
    for (int p = 0; p < 24; p++) {
        int idx = p * 256 + tid;
        int op = idx >> 11, rem = idx & 2047;
        int h = rem >> 10, r = (rem >> 3) & 127, seg = rem & 7;
        uint32_t off = (uint32_t)(op * 2 * SUB_BYTES + h * SUB_BYTES)
                     + swz((uint32_t)(r * 128 + seg * 16));
        int col = c * 64 + h * 32 + seg * 4;
        const float* src;
        bool valid = true;
        if (op == 2) {
            src = F + (size_t)(b0 + r) * HID + col;
        } else {
            int m = m0 + op * 128 + r;
            valid = (m < MC);
            src = W + (size_t)(valid ? m : 0) * HID + col;
        }
        cp16(st + off, src, valid);
    }
}
#endif

__global__ void __launch_bounds__(256, 1) k_stage2(const float* __restrict__ F,
                                                   const float* __restrict__ W,
                                                   float* __restrict__ out) {
    int tid = threadIdx.x, wid = tid >> 5, lane = tid & 31;

    if (blockIdx.x >= 104) {
        // ---------------- su: 32 blocks x 16 k each ----------------
        __shared__ float sh_s[4][2], sh_u[4][2];
        __shared__ double sh_d[4][2];
        int blk = (int)blockIdx.x - 104;
        int kl = wid >> 1, half = wid & 1;
        double s2acc = 0.0, usacc = 0.0;
        for (int j = 0; j < 4; j++) {
            int k = blk * 16 + kl * 4 + j;
            const float4* row = reinterpret_cast<const float4*>(g_Wt + (size_t)k * 4096)
                              + half * 500;
            const float4* av  = reinterpret_cast<const float4*>(g_a) + half * 500;
            float s = 0.f, u = 0.f;
            #pragma unroll
            for (int q = 0; q < 16; q++) {
                int idx = lane + q * 32;
                if (idx < 500) {
                    float4 w = row[idx];
                    float4 a = av[idx];
                    s += w.x + w.y + w.z + w.w;
                    u += a.x*w.x + a.y*w.y + a.z*w.z + a.w*w.w;
                }
            }
            #pragma unroll
            for (int o = 16; o > 0; o >>= 1) {
                s += __shfl_down_sync(0xffffffffu, s, o);
                u += __shfl_down_sync(0xffffffffu, u, o);
            }
            if (lane == 0) { sh_s[kl][half] = s; sh_u[kl][half] = u; }
            __syncthreads();
            if (tid < 4) {
                float sk = sh_s[tid][0] + sh_s[tid][1];
                float uk = sh_u[tid][0] + sh_u[tid][1];
                sh_d[tid][0] = (double)sk * (double)sk;
                sh_d[tid][1] = (double)uk * (double)sk;
            }
            __syncthreads();
            if (tid == 0) {
                #pragma unroll
                for (int i = 0; i < 4; i++) { s2acc += sh_d[i][0]; usacc += sh_d[i][1]; }
            }
            __syncthreads();
        }
        if (tid == 0) { g_s2p[blk] = s2acc; g_usp[blk] = usacc; }
        return;
    }

#if HAS_TC
    extern __shared__ char smem[];
    uint32_t sb = smem_u32(smem);

    if (blockIdx.x < 40) {
        // ---------------- gram: 10 tiles x 4 z of 1024 m, 16 chunks ----------------
        int t = blockIdx.x >> 2, z = blockIdx.x & 3;
        int K0 = c_ti[t] * 128, L0 = c_tj[t] * 128, mbase = z * 1024;
        const int NCH = 16;

        if (tid < 2) MBAR_INIT(sb + tid * 8, 1);
        if (wid == 0) { TC_ALLOC(sb + 32, 128); TC_RELINQ(); }
        __syncthreads();
        uint32_t tmem;
        asm volatile("ld.shared.b32 %0, [%1];" : "=r"(tmem) : "r"(sb + 32));

        gram_load_chunk(sb, 0, 0, K0, L0, mbase, tid);
        asm volatile("cp.async.commit_group;" ::: "memory");
        uint32_t phv = 0;
        for (int c = 0; c < NCH; c++) {
            int s = c & 1;
            if (c + 1 < NCH) {
                int so = (c + 1) & 1;
                if (c >= 1) {
                    MBAR_WAIT(sb + so * 8, (phv >> so) & 1u);
                    phv ^= (1u << so);
                }
                gram_load_chunk(sb, so, c + 1, K0, L0, mbase, tid);
            }
            asm volatile("cp.async.commit_group;" ::: "memory");
            asm volatile("cp.async.wait_group 1;" ::: "memory");
            __syncthreads();
            if (wid == 0 && elect_one()) {
                asm volatile("fence.proxy.async.shared::cta;" ::: "memory");
                uint32_t st = sb + 1024 + s * G_STG;
                #pragma unroll
                for (int h = 0; h < 2; h++) {
                    uint64_t ad = make_desc(st + h * SUB_BYTES);
                    uint64_t bd = make_desc(st + 2 * SUB_BYTES + h * SUB_BYTES);
                    #pragma unroll
                    for (int k = 0; k < 4; k++)
                        mma_tf32(tmem, ad + k * 2, bd + k * 2, IDESC_TF32,
                                 (c > 0 || h > 0 || k > 0) ? 1u : 0u);
                }
                TC_COMMIT(sb + s * 8);
            }
        }
        __syncthreads();
        {
            int so = (NCH - 1) & 1;
            MBAR_WAIT(sb + so * 8, (phv >> so) & 1u);
        }
        TC_FENCE_AFTER();

        float* dst = g_G2 + ((size_t)blockIdx.x << 14);
        int row = (wid & 3) * 32 + lane;
        int cb = (wid >> 2) * 64;
        #pragma unroll
        for (int j0 = 0; j0 < 64; j0 += 32) {
            uint32_t r[32];
            LDTM_X32(r, tmem + cb + j0);
            TC_WAIT_LD();
            #pragma unroll
            for (int j4 = 0; j4 < 8; j4++) {
                float4 v = make_float4(__uint_as_float(r[j4*4+0]), __uint_as_float(r[j4*4+1]),
                                       __uint_as_float(r[j4*4+2]), __uint_as_float(r[j4*4+3]));
                *reinterpret_cast<float4*>(&dst[(size_t)row * 128 + cb + j0 + j4 * 4]) = v;
            }
        }
        TC_FENCE_BEFORE();
        __syncthreads();
        if (wid == 0) TC_DEALLOC(tmem, 128);
    } else {
        // ---------------- fw: 64 CTAs = 16 m-pairs x 4 b-tiles, 8 chunks ----------
        int fwid = (int)blockIdx.x - 40;
        int m0 = (fwid & 15) * 256, b0 = (fwid >> 4) * 128;
        const int NCH = 8;

        if (tid < 2) MBAR_INIT(sb + tid * 8, 1);
        if (wid == 0) { TC_ALLOC(sb + 32, 256); TC_RELINQ(); }
        __syncthreads();
        uint32_t tmem;
        asm volatile("ld.shared.b32 %0, [%1];" : "=r"(tmem) : "r"(sb + 32));

        fw_load_chunk(sb, 0, 0, W, F, m0, b0, tid);
        asm volatile("cp.async.commit_group;" ::: "memory");
        uint32_t phv = 0;
        for (int c = 0; c < NCH; c++) {
            int s = c & 1;
            if (c + 1 < NCH) {
                int so = (c + 1) & 1;
                if (c >= 1) {
                    MBAR_WAIT(sb + so * 8, (phv >> so) & 1u);
                    phv ^= (1u << so);
                }
                fw_load_chunk(sb, so, c + 1, W, F, m0, b0, tid);
            }
            asm volatile("cp.async.commit_group;" ::: "memory");
            asm volatile("cp.async.wait_group 1;" ::: "memory");
            __syncthreads();
            if (wid == 0 && elect_one()) {
                asm volatile("fence.proxy.async.shared::cta;" ::: "memory");
                uint32_t st = sb + 1024 + s * F_STG;
                #pragma unroll
                for (int h = 0; h < 2; h++) {
                    uint64_t a0 = make_desc(st + h * SUB_BYTES);
                    uint64_t a1 = make_desc(st + 2 * SUB_BYTES + h * SUB_BYTES);
                    uint64_t bd = make_desc(st + 4 * SUB_BYTES + h * SUB_BYTES);
                    #pragma unroll
                    for (int k = 0; k < 4; k++) {
                        uint32_t en = (c > 0 || h > 0 || k > 0) ? 1u : 0u;
                        mma_tf32(tmem,       a0 + k * 2, bd + k * 2, IDESC_TF32, en);
                        mma_tf32(tmem + 128, a1 + k * 2, bd + k * 2, IDESC_TF32, en);
                    }
                }
                TC_COMMIT(sb + s * 8);
            }
        }
        __syncthreads();
        {
            int so = (NCH - 1) & 1;
            MBAR_WAIT(sb + so * 8, (phv >> so) & 1u);
        }
        TC_FENCE_AFTER();

        // epilogue over both m-halves
        int cb = (wid >> 2) * 64;
        #pragma unroll
        for (int t2 = 0; t2 < 2; t2++) {
            int m = m0 + t2 * 128 + (wid & 3) * 32 + lane;
            float a = (m < MC) ? __ldg(&g_a[m]) : __int_as_float(0x7f800000);
            int grp = m >> 2;
            #pragma unroll
            for (int j0 = 0; j0 < 64; j0 += 32) {
                uint32_t r[32];
                LDTM_X32(r, tmem + t2 * 128 + cb + j0);
                TC_WAIT_LD();
                #pragma unroll
                for (int jj = 0; jj < 32; jj++) {
                    float fw = __uint_as_float(r[jj]);
                    float x = fmaf(-2.f, fw, a);
                    x = fminf(x, __shfl_xor_sync(0xffffffffu, x, 1));
                    x = fminf(x, __shfl_xor_sync(0xffffffffu, x, 2));
                    if ((lane & 3) == 0 && m < MC) {
                        int b = b0 + cb + j0 + jj;
                        out[(size_t)b * (NCLS + 1) + grp] =
                            expf(-(__ldg(&g_fsq[b]) + x) * INV_SIGMA);
                    }
                }
            }
        }
        TC_FENCE_BEFORE();
        __syncthreads();
        if (wid == 0) TC_DEALLOC(tmem, 256);
    }
#else
    // correct fallbacks (never selected on GB300)
    if (blockIdx.x < 40) {
        int t = blockIdx.x >> 2, z = blockIdx.x & 3;
        int K0 = c_ti[t] * 128, L0 = c_tj[t] * 128, mbase = z * 1024;
        float* dst = g_G2 + ((size_t)blockIdx.x << 14);
        for (int e = tid; e < 16384; e += blockDim.x) {
            int k = K0 + (e >> 7), l = L0 + (e & 127);
            float acc = 0.f;
            for (int m = 0; m < 1024; m++)
                acc = fmaf(g_Wt[(size_t)k * 4096 + mbase + m],
                           g_Wt[(size_t)l * 4096 + mbase + m], acc);
            dst[e] = acc;
        }
    } else {
        int fwid = (int)blockIdx.x - 40;
        int m0 = (fwid & 15) * 256, b0 = (fwid >> 4) * 128;
        for (int t2 = 0; t2 < 2; t2++) {
            int m = m0 + t2 * 128 + (tid & 127);
            if (m >= MC || tid >= 128) continue;
            float a = g_a[m];
            int grp = m >> 2;
            const float* wrow = W + (size_t)m * HID;
            for (int jb = 0; jb < 128; jb++) {
                int b = b0 + jb;
                const float* frow = F + (size_t)b * HID;
                float dot = 0.f;
                for (int k = 0; k < HID; k++) dot = fmaf(wrow[k], frow[k], dot);
                float x = fmaf(-2.f, dot, a);
                x = fminf(x, __shfl_xor_sync(0xffffffffu, x, 1));
                x = fminf(x, __shfl_xor_sync(0xffffffffu, x, 2));
                if ((tid & 3) == 0)
                    out[(size_t)b * (NCLS + 1) + grp] =
                        expf(-(g_fsq[b] + x) * INV_SIGMA);
            }
        }
    }
#endif
}

// ---------------- f2 + fused finalize (last-arriving block) ----------------
__global__ void __launch_bounds__(256) k_f2fin(float* __restrict__ out) {
    __shared__ double sd[8], sd2[8], sd3[8], sd4[8], sd5[8];
    __shared__ bool is_last;
    __shared__ float rw_s;
    int tid = threadIdx.x, wid = tid >> 5, lane = tid & 31;

    double acc = 0.0;
    for (int i = (int)blockIdx.x * 256 + tid; i < 10 * 16384; i += 160 * 256) {
        int t = i >> 14, e = i & 16383;
        float g = 0.f;
        #pragma unroll
        for (int z = 0; z < 4; z++) g += g_G2[((size_t)(t * 4 + z) << 14) + e];
        double w = (c_ti[t] == c_tj[t]) ? 1.0 : 2.0;
        acc += w * (double)g * (double)g;
    }
    #pragma unroll
    for (int o = 16; o > 0; o >>= 1)
        acc += __shfl_down_sync(0xffffffffu, acc, o);
    if (lane == 0) sd[wid] = acc;
    __syncthreads();
    if (tid == 0) {
        double f = 0.0;
        #pragma unroll
        for (int j = 0; j < 8; j++) f += sd[j];
        g_f2p[blockIdx.x] = f;
    }
    __threadfence();
    __syncthreads();
    if (tid == 0) {
        unsigned v = atomicAdd(&g_ctr, 1u);
        is_last = (v == 159u);
    }
    __syncthreads();
    if (!is_last) return;
    if (tid == 0) g_ctr = 0;
    __threadfence();

    double la  = (tid < 141) ? g_ap[tid]  : 0.0;
    double la2 = (tid < 141) ? g_a2p[tid] : 0.0;
    double ls2 = (tid < 32)  ? g_s2p[tid] : 0.0;
    double lus = (tid < 32)  ? g_usp[tid] : 0.0;
    double lf2 = (tid < 160) ? g_f2p[tid] : 0.0;
    #pragma unroll
    for (int o = 16; o > 0; o >>= 1) {
        la  += __shfl_down_sync(0xffffffffu, la,  o);
        la2 += __shfl_down_sync(0xffffffffu, la2, o);
        ls2 += __shfl_down_sync(0xffffffffu, ls2, o);
        lus += __shfl_down_sync(0xffffffffu, lus, o);
        lf2 += __shfl_down_sync(0xffffffffu, lf2, o);
    }
    if (lane == 0) { sd[wid]=la; sd2[wid]=la2; sd3[wid]=ls2; sd4[wid]=lus; sd5[wid]=lf2; }
    __syncthreads();
    if (tid == 0) {
        double sum_a=0, sum_a2=0, s2=0, sum_at=0, F2=0;
        #pragma unroll
        for (int j = 0; j < 8; j++) {
            sum_a += sd[j]; sum_a2 += sd2[j]; s2 += sd3[j];
            sum_at += sd4[j]; F2 += sd5[j];
        }
        double mc = (double)MC;
        double denom = 2.0 / (mc * mc - mc);
        double S1 = mc * sum_a - s2;
        double mu = denom * S1;
        double S2 = mc * sum_a2 + sum_a * sum_a + 2.0 * F2 - 4.0 * sum_at;
        rw_s = (float)(denom * S2 - mu * mu);
    }
    __syncthreads();
    #pragma unroll
    for (int j = 0; j < 2; j++)
        out[(size_t)(tid * 2 + j) * (NCLS + 1) + NCLS] = rw_s;
}

extern "C" void kernel_launch(void* const* d_in, const int* in_sizes, int n_in,
                              void* d_out, int out_size) {
    const float* F = (const float*)d_in[0];   // [512,512]
    const float* W = (const float*)d_in[1];   // [4000,512]
    float* out = (float*)d_out;               // [512,1001]
    (void)in_sizes; (void)n_in; (void)out_size;

    static bool inited = false;
    if (!inited) {
        cudaFuncSetAttribute(k_stage2, cudaFuncAttributeMaxDynamicSharedMemorySize,
                             SMEM_TC);
        inited = true;
    }

    k_stage1<<<2189, 256>>>(W, F);               // transpose || pre
    k_stage2<<<136, 256, SMEM_TC>>>(F, W, out);  // gram || fw || su — one wave
    k_f2fin<<<160, 256>>>(out);                  // f2 + fused finalize
}